// round 1
// baseline (speedup 1.0000x reference)
#include <cuda_runtime.h>
#include <cuda_bf16.h>

// SSIM loss, fully fused. Layout: (1, 3, 2048, 2048) fp32, VALID 11-tap separable
// Gaussian (sigma=1.5). Output: scalar fp32 = 1 - mean(ssim_map) over (3,2038,2038).

#define H_DIM 2048
#define W_DIM 2048
#define OUT_DIM 2038          // 2048 - 11 + 1
#define TILE 32               // output tile (cols and rows)
#define HALO 10
#define IN_TILE 42            // TILE + HALO
#define NTHREADS 128

__device__ double g_ssim_sum;

__global__ void ssim_init_kernel() { g_ssim_sum = 0.0; }

__global__ __launch_bounds__(NTHREADS)
void ssim_main_kernel(const float* __restrict__ xin, const float* __restrict__ yin) {
    // SMEM: input tile (stride 43 -> conflict-free for 8-row x 4-run warp pattern),
    // horizontal-blur maps (stride 33 -> conflict-free stores & vertical reads).
    __shared__ float sx[IN_TILE][43];
    __shared__ float sy[IN_TILE][43];
    __shared__ float hb[5][IN_TILE][33];
    __shared__ float red[4];

    const int tid = threadIdx.x;
    const int gx0 = blockIdx.x * TILE;
    const int gy0 = blockIdx.y * TILE;
    const float* __restrict__ xp = xin + (size_t)blockIdx.z * (H_DIM * W_DIM);
    const float* __restrict__ yp = yin + (size_t)blockIdx.z * (H_DIM * W_DIM);

    // Gaussian weights (exactly the reference formula), normalized.
    float w[11];
    float wsum = 0.0f;
    #pragma unroll
    for (int i = 0; i < 11; ++i) {
        float d = (float)(i - 5);
        w[i] = expf(-d * d * (1.0f / 4.5f));
        wsum += w[i];
    }
    float winv = 1.0f / wsum;
    #pragma unroll
    for (int i = 0; i < 11; ++i) w[i] *= winv;

    // ---- Load x,y input tile (42x42 with zero clamp at image edge) ----
    for (int i = tid; i < IN_TILE * IN_TILE; i += NTHREADS) {
        int r = i / IN_TILE;
        int c = i - r * IN_TILE;
        int gr = gy0 + r;
        int gc = gx0 + c;
        float xv = 0.0f, yv = 0.0f;
        if (gr < H_DIM && gc < W_DIM) {
            int idx = gr * W_DIM + gc;
            xv = __ldg(xp + idx);
            yv = __ldg(yp + idx);
        }
        sx[r][c] = xv;
        sy[r][c] = yv;
    }
    __syncthreads();

    // ---- Phase A: horizontal blur of 5 maps, register sliding window ----
    // 42 rows x 32 cols of hblur points; tasks = 42 rows x 4 runs of 8 cols.
    for (int task = tid; task < IN_TILE * 4; task += NTHREADS) {
        int r  = task >> 2;
        int c0 = (task & 3) << 3;
        float ax[8]  = {0,0,0,0,0,0,0,0};
        float ay[8]  = {0,0,0,0,0,0,0,0};
        float axx[8] = {0,0,0,0,0,0,0,0};
        float ayy[8] = {0,0,0,0,0,0,0,0};
        float axy[8] = {0,0,0,0,0,0,0,0};
        #pragma unroll
        for (int k = 0; k < 18; ++k) {
            float xv = sx[r][c0 + k];
            float yv = sy[r][c0 + k];
            float xx = xv * xv;
            float yy = yv * yv;
            float xy = xv * yv;
            #pragma unroll
            for (int j = 0; j < 8; ++j) {
                int t = k - j;
                if (t >= 0 && t < 11) {
                    float wt = w[t];
                    ax[j]  = fmaf(wt, xv, ax[j]);
                    ay[j]  = fmaf(wt, yv, ay[j]);
                    axx[j] = fmaf(wt, xx, axx[j]);
                    ayy[j] = fmaf(wt, yy, ayy[j]);
                    axy[j] = fmaf(wt, xy, axy[j]);
                }
            }
        }
        #pragma unroll
        for (int j = 0; j < 8; ++j) {
            hb[0][r][c0 + j] = ax[j];
            hb[1][r][c0 + j] = ay[j];
            hb[2][r][c0 + j] = axx[j];
            hb[3][r][c0 + j] = ayy[j];
            hb[4][r][c0 + j] = axy[j];
        }
    }
    __syncthreads();

    // ---- Phase B: vertical blur (sliding window) + SSIM + reduce ----
    const int tx  = tid & 31;          // output column within tile
    const int tg  = tid >> 5;          // row-group 0..3, each owns 8 output rows
    const int oyb = tg << 3;

    float m1[8]  = {0,0,0,0,0,0,0,0};
    float m2[8]  = {0,0,0,0,0,0,0,0};
    float e11[8] = {0,0,0,0,0,0,0,0};
    float e22[8] = {0,0,0,0,0,0,0,0};
    float e12[8] = {0,0,0,0,0,0,0,0};
    #pragma unroll
    for (int k = 0; k < 18; ++k) {
        int rr = oyb + k;
        float v0 = hb[0][rr][tx];
        float v1 = hb[1][rr][tx];
        float v2 = hb[2][rr][tx];
        float v3 = hb[3][rr][tx];
        float v4 = hb[4][rr][tx];
        #pragma unroll
        for (int j = 0; j < 8; ++j) {
            int t = k - j;
            if (t >= 0 && t < 11) {
                float wt = w[t];
                m1[j]  = fmaf(wt, v0, m1[j]);
                m2[j]  = fmaf(wt, v1, m2[j]);
                e11[j] = fmaf(wt, v2, e11[j]);
                e22[j] = fmaf(wt, v3, e22[j]);
                e12[j] = fmaf(wt, v4, e12[j]);
            }
        }
    }

    const float C1 = 0.01f * 0.01f;
    const float C2 = 0.03f * 0.03f;
    float lsum = 0.0f;
    const int ox = gx0 + tx;
    #pragma unroll
    for (int j = 0; j < 8; ++j) {
        int oy = gy0 + oyb + j;
        if (oy < OUT_DIM && ox < OUT_DIM) {
            float mu1 = m1[j], mu2 = m2[j];
            float m11 = mu1 * mu1;
            float m22 = mu2 * mu2;
            float m12 = mu1 * mu2;
            float s1  = e11[j] - m11;
            float s2  = e22[j] - m22;
            float s12 = e12[j] - m12;
            float num = (2.0f * m12 + C1) * (2.0f * s12 + C2);
            float den = (m11 + m22 + C1) * (s1 + s2 + C2);
            lsum += __fdividef(num, den);
        }
    }

    // warp reduce
    #pragma unroll
    for (int off = 16; off > 0; off >>= 1)
        lsum += __shfl_down_sync(0xffffffffu, lsum, off);
    if (tx == 0) red[tg] = lsum;
    __syncthreads();
    if (tid == 0) {
        float bs = red[0] + red[1] + red[2] + red[3];
        atomicAdd(&g_ssim_sum, (double)bs);
    }
}

__global__ void ssim_finalize_kernel(float* out) {
    double n = 3.0 * (double)OUT_DIM * (double)OUT_DIM;
    out[0] = 1.0f - (float)(g_ssim_sum / n);
}

extern "C" void kernel_launch(void* const* d_in, const int* in_sizes, int n_in,
                              void* d_out, int out_size) {
    const float* pred = (const float*)d_in[0];
    const float* targ = (const float*)d_in[1];
    float* out = (float*)d_out;

    ssim_init_kernel<<<1, 1>>>();
    dim3 grid((W_DIM + TILE - 1) / TILE, (H_DIM + TILE - 1) / TILE, 3);  // 64x64x3
    ssim_main_kernel<<<grid, NTHREADS>>>(pred, targ);
    ssim_finalize_kernel<<<1, 1>>>(out);
}

// round 2
// speedup vs baseline: 1.6290x; 1.6290x over previous
#include <cuda_runtime.h>
#include <cuda_bf16.h>

// SSIM loss, fully fused. (1,3,2048,2048) fp32, VALID 11-tap separable Gaussian
// (sigma=1.5). Output scalar fp32 = 1 - mean(ssim_map) over (3,2038,2038).
//
// Key perf levers vs v1:
//  - Gaussian weights hardcoded as literals -> FFMA-imm form (rt=1, 2x tput)
//  - predicate-free 11-tap dot products (no 144-vs-88 predicated waste)
//  - per-block partial sums + reduce kernel (no init kernel, no fp64 atomics)

#define H_DIM 2048
#define W_DIM 2048
#define OUT_DIM 2038
#define TILE 32
#define IN_TILE 42
#define NTHREADS 128
#define GRID_X 64
#define GRID_Y 64
#define NBLOCKS (GRID_X * GRID_Y * 3)

// Normalized gaussian(sigma=1.5, size=11) weights; sum == 1.0f exactly.
#define W0 0.00102841f
#define W1 0.00759878f
#define W2 0.03600077f
#define W3 0.10936067f
#define W4 0.21300553f
#define W5 0.26601168f

__device__ float g_partial[NBLOCKS];

// 11-tap dot products over an 18-wide window -> 8 outputs, all FFMA-imm.
__device__ __forceinline__ void conv11(const float* __restrict__ v,
                                       float* __restrict__ acc) {
    const float W[11] = {W0, W1, W2, W3, W4, W5, W4, W3, W2, W1, W0};
    #pragma unroll
    for (int j = 0; j < 8; ++j) {
        float a = W0 * v[j];
        #pragma unroll
        for (int t = 1; t < 11; ++t)
            a = fmaf(W[t], v[j + t], a);
        acc[j] = a;
    }
}

__global__ __launch_bounds__(NTHREADS)
void ssim_main_kernel(const float* __restrict__ xin, const float* __restrict__ yin) {
    __shared__ float sx[IN_TILE][43];   // stride 43: conflict-free window loads
    __shared__ float sy[IN_TILE][43];
    __shared__ float hb[5][IN_TILE][33]; // stride 33: conflict-free ST + vert LD
    __shared__ float red[4];

    const int tid = threadIdx.x;
    const int gx0 = blockIdx.x * TILE;
    const int gy0 = blockIdx.y * TILE;
    const float* __restrict__ xp = xin + (size_t)blockIdx.z * (H_DIM * W_DIM);
    const float* __restrict__ yp = yin + (size_t)blockIdx.z * (H_DIM * W_DIM);

    // ---- Load 42x42 x,y tile (zero clamp at image edge) ----
    #pragma unroll
    for (int i = tid; i < IN_TILE * IN_TILE; i += NTHREADS) {
        int r = i / IN_TILE;
        int c = i - r * IN_TILE;
        int gr = gy0 + r;
        int gc = gx0 + c;
        float xv = 0.0f, yv = 0.0f;
        if (gr < H_DIM && gc < W_DIM) {
            int idx = gr * W_DIM + gc;
            xv = __ldg(xp + idx);
            yv = __ldg(yp + idx);
        }
        sx[r][c] = xv;
        sy[r][c] = yv;
    }
    __syncthreads();

    // ---- Phase A: horizontal blur of 5 maps (x, y, xy, xx, yy) ----
    // 42 rows x 4 runs of 8 cols = 168 tasks.
    for (int task = tid; task < IN_TILE * 4; task += NTHREADS) {
        int r  = task >> 2;
        int c0 = (task & 3) << 3;
        float xw[18], yw[18], pw[18], acc[8];

        #pragma unroll
        for (int k = 0; k < 18; ++k) xw[k] = sx[r][c0 + k];
        conv11(xw, acc);
        #pragma unroll
        for (int j = 0; j < 8; ++j) hb[0][r][c0 + j] = acc[j];

        #pragma unroll
        for (int k = 0; k < 18; ++k) yw[k] = sy[r][c0 + k];
        conv11(yw, acc);
        #pragma unroll
        for (int j = 0; j < 8; ++j) hb[1][r][c0 + j] = acc[j];

        #pragma unroll
        for (int k = 0; k < 18; ++k) pw[k] = xw[k] * yw[k];
        conv11(pw, acc);
        #pragma unroll
        for (int j = 0; j < 8; ++j) hb[4][r][c0 + j] = acc[j];

        #pragma unroll
        for (int k = 0; k < 18; ++k) pw[k] = xw[k] * xw[k];
        conv11(pw, acc);
        #pragma unroll
        for (int j = 0; j < 8; ++j) hb[2][r][c0 + j] = acc[j];

        #pragma unroll
        for (int k = 0; k < 18; ++k) pw[k] = yw[k] * yw[k];
        conv11(pw, acc);
        #pragma unroll
        for (int j = 0; j < 8; ++j) hb[3][r][c0 + j] = acc[j];
    }
    __syncthreads();

    // ---- Phase B: vertical blur + SSIM + block reduction ----
    const int tx  = tid & 31;      // output column
    const int tg  = tid >> 5;      // row-group 0..3 (8 output rows each)
    const int oyb = tg << 3;

    float acc[5][8];
    #pragma unroll
    for (int m = 0; m < 5; ++m) {
        float v[18];
        #pragma unroll
        for (int k = 0; k < 18; ++k) v[k] = hb[m][oyb + k][tx];
        conv11(v, acc[m]);
    }

    const float C1 = 0.01f * 0.01f;
    const float C2 = 0.03f * 0.03f;
    float lsum = 0.0f;
    const int ox = gx0 + tx;
    #pragma unroll
    for (int j = 0; j < 8; ++j) {
        int oy = gy0 + oyb + j;
        if (oy < OUT_DIM && ox < OUT_DIM) {
            float mu1 = acc[0][j], mu2 = acc[1][j];
            float m11 = mu1 * mu1;
            float m22 = mu2 * mu2;
            float m12 = mu1 * mu2;
            float s1  = acc[2][j] - m11;
            float s2  = acc[3][j] - m22;
            float s12 = acc[4][j] - m12;
            float num = (2.0f * m12 + C1) * (2.0f * s12 + C2);
            float den = (m11 + m22 + C1) * (s1 + s2 + C2);
            lsum += __fdividef(num, den);
        }
    }

    #pragma unroll
    for (int off = 16; off > 0; off >>= 1)
        lsum += __shfl_down_sync(0xffffffffu, lsum, off);
    if (tx == 0) red[tg] = lsum;
    __syncthreads();
    if (tid == 0) {
        int bid = (blockIdx.z * GRID_Y + blockIdx.y) * GRID_X + blockIdx.x;
        g_partial[bid] = red[0] + red[1] + red[2] + red[3];
    }
}

__global__ __launch_bounds__(1024)
void ssim_final_kernel(float* __restrict__ out) {
    __shared__ double s[32];
    double sum = 0.0;
    for (int i = threadIdx.x; i < NBLOCKS; i += 1024)
        sum += (double)g_partial[i];
    #pragma unroll
    for (int off = 16; off > 0; off >>= 1)
        sum += __shfl_down_sync(0xffffffffu, sum, off);
    int lane = threadIdx.x & 31, wid = threadIdx.x >> 5;
    if (lane == 0) s[wid] = sum;
    __syncthreads();
    if (wid == 0) {
        double v = s[lane];
        #pragma unroll
        for (int off = 16; off > 0; off >>= 1)
            v += __shfl_down_sync(0xffffffffu, v, off);
        if (lane == 0) {
            double n = 3.0 * (double)OUT_DIM * (double)OUT_DIM;
            out[0] = 1.0f - (float)(v / n);
        }
    }
}

extern "C" void kernel_launch(void* const* d_in, const int* in_sizes, int n_in,
                              void* d_out, int out_size) {
    const float* pred = (const float*)d_in[0];
    const float* targ = (const float*)d_in[1];
    float* out = (float*)d_out;

    dim3 grid(GRID_X, GRID_Y, 3);
    ssim_main_kernel<<<grid, NTHREADS>>>(pred, targ);
    ssim_final_kernel<<<1, 1024>>>(out);
}